// round 12
// baseline (speedup 1.0000x reference)
#include <cuda_runtime.h>

#define DIN     4096
#define DOUT    4096
#define RNK     16
#define NROWS   8192            // 4*2048

// ---------------- K1 geometry ----------------
#define K1_THREADS 128
#define K1_RPW     8            // rows per warp
#define K1_ROWS    32           // rows per block (4 warps x 8)
#define KSPLIT     4
#define KQ         (DIN / KSPLIT)        // 1024
#define K1_KT      64                    // k per pipeline tile
#define K1_NST     3
#define K1_TILES   (KQ / K1_KT)          // 16
#define ATP        68                    // A_T row pitch in floats (== 4 mod 32)
#define XS_F       (K1_ROWS * K1_KT)     // 2048 floats x-stage
#define AS_F       (RNK * ATP)           // 1088 floats A_T-stage
#define STG_F      (XS_F + AS_F)         // 3136 floats
#define K1_GRID    (NROWS / K1_ROWS * KSPLIT)   // 1024

// ---------------- K2 geometry ----------------
#define K2_THREADS 128
#define K2_ROWS    32
#define K2_CBLK    8                     // column blocks of 512
#define K2_GRID    ((NROWS / K2_ROWS) * K2_CBLK)   // 2048

// scratch: t partials + transposed operands
__device__ float g_t[NROWS * KSPLIT * RNK];   // 2 MB
__device__ float g_At[RNK * DIN];             // 256 KB: A_T[r][k]
__device__ float g_Bt[DOUT * RNK];            // 256 KB: B_T[j][r]

__device__ __forceinline__ void ffma2(unsigned long long &acc,
                                      unsigned long long a, unsigned long long b) {
    asm("fma.rn.f32x2 %0, %1, %2, %0;" : "+l"(acc) : "l"(a), "l"(b));
}
__device__ __forceinline__ unsigned long long add2(unsigned long long a,
                                                   unsigned long long b) {
    unsigned long long d;
    asm("add.rn.f32x2 %0, %1, %2;" : "=l"(d) : "l"(a), "l"(b));
    return d;
}
__device__ __forceinline__ void unpk2(float &lo, float &hi, unsigned long long v) {
    asm("mov.b64 {%0, %1}, %2;" : "=f"(lo), "=f"(hi) : "l"(v));
}
__device__ __forceinline__ unsigned su32(const void* p) {
    unsigned a;
    asm("{ .reg .u64 t; cvta.to.shared.u64 t, %1; cvt.u32.u64 %0, t; }"
        : "=r"(a) : "l"(p));
    return a;
}
__device__ __forceinline__ void cpa16(unsigned d, const void* s) {
    asm volatile("cp.async.cg.shared.global [%0], [%1], 16;" :: "r"(d), "l"(s));
}

// ======= K0: transpose A and B (one launch, coalesced reads) =======
__global__ void lora_k0(const float* __restrict__ A, const float* __restrict__ B) {
    const int i = blockIdx.x * 256 + threadIdx.x;      // 0 .. 64K-1
    // A [4096 k][16 r] -> g_At[16][4096]
    { int k = i >> 4,  r = i & 15;    g_At[r * DIN + k] = A[i]; }
    // B [16 r][4096 j] -> g_Bt[4096][16]
    { int r = i >> 12, j = i & 4095;  g_Bt[j * RNK + r] = B[i]; }
}

// ============ K1: t_partial = x @ A  (k-paired f32x2) ============
__global__ void __launch_bounds__(K1_THREADS, 6)
lora_k1(const float* __restrict__ x)
{
    __shared__ float sm[K1_NST * STG_F];     // ~36.8 KB: x + A_T tiles

    const int tid  = threadIdx.x;
    const int lane = tid & 31;
    const int warp = tid >> 5;
    const int g    = lane & 7;               // rank-group: owns ranks g, g+8
    const int ksub = lane >> 3;              // k-quarter within a 16-k batch
    const int rb    = blockIdx.x >> 2;
    const int split = blockIdx.x & 3;
    const int k0    = split * KQ;
    const long long rowBase = (long long)rb * K1_ROWS;
    const int       warpRow0 = warp * K1_RPW;
    const unsigned  smb = su32(sm);

    auto issue = [&](int tile, int stg) {
        const unsigned xs = smb + (unsigned)(stg * STG_F) * 4u;
        const unsigned as = xs + XS_F * 4u;
        const long long gk = k0 + tile * K1_KT;
        #pragma unroll
        for (int m = 0; m < 4; m++) {
            int q   = tid + m * K1_THREADS;
            int row = q >> 4, c = q & 15;
            cpa16(xs + (unsigned)(row * K1_KT + c * 4) * 4u,
                  x + (rowBase + row) * DIN + gk + c * 4);
        }
        #pragma unroll
        for (int m = 0; m < 2; m++) {
            int q = tid + m * K1_THREADS;
            int r = q >> 4, c = q & 15;
            cpa16(as + (unsigned)(r * ATP + c * 4) * 4u,
                  g_At + (long long)r * DIN + gk + c * 4);
        }
    };

    issue(0, 0); asm volatile("cp.async.commit_group;");
    issue(1, 1); asm volatile("cp.async.commit_group;");

    unsigned long long acc[K1_RPW][2];
    #pragma unroll
    for (int r = 0; r < K1_RPW; r++) { acc[r][0] = 0ULL; acc[r][1] = 0ULL; }

    #pragma unroll 1
    for (int t = 0; t < K1_TILES; t++) {
        asm volatile("cp.async.wait_group %0;" :: "n"(1));
        __syncthreads();
        if (t + 2 < K1_TILES) issue(t + 2, (t + 2) % K1_NST);
        asm volatile("cp.async.commit_group;");

        const float* xs = sm + (t % K1_NST) * STG_F;
        const float* ap = xs + XS_F + g * ATP;
        const float* xp = xs + warpRow0 * K1_KT + 4 * ksub;

        #pragma unroll
        for (int b = 0; b < K1_KT / 16; b++) {
            const int kb = b * 16 + 4 * ksub;
            ulonglong2 aA = *reinterpret_cast<const ulonglong2*>(ap + kb);
            ulonglong2 aB = *reinterpret_cast<const ulonglong2*>(ap + 8 * ATP + kb);

            #pragma unroll
            for (int r = 0; r < K1_RPW; r++) {
                ulonglong2 xv = *reinterpret_cast<const ulonglong2*>(
                                    xp + r * K1_KT + b * 16);
                ffma2(acc[r][0], xv.x, aA.x);
                ffma2(acc[r][0], xv.y, aA.y);
                ffma2(acc[r][1], xv.x, aB.x);
                ffma2(acc[r][1], xv.y, aB.y);
            }
        }
    }

    #pragma unroll
    for (int r = 0; r < K1_RPW; r++) {
        #pragma unroll
        for (int h = 0; h < 2; h++) {
            acc[r][h] = add2(acc[r][h], __shfl_xor_sync(0xffffffffu, acc[r][h], 8));
            acc[r][h] = add2(acc[r][h], __shfl_xor_sync(0xffffffffu, acc[r][h], 16));
        }
    }
    if (ksub == 0) {
        #pragma unroll
        for (int r = 0; r < K1_RPW; r++) {
            long long row = rowBase + warpRow0 + r;
            float lo, hi, t0, t1;
            unpk2(lo, hi, acc[r][0]); t0 = lo + hi;
            unpk2(lo, hi, acc[r][1]); t1 = lo + hi;
            float* dst = &g_t[row * (KSPLIT * RNK) + split * RNK];
            dst[g]     = t0;
            dst[g + 8] = t1;
        }
    }
}

// ===== K2: out = (sum_s t_s) @ B — rank-paired f32x2, no MOVs =====
__global__ void __launch_bounds__(K2_THREADS, 5)
lora_k2(float* __restrict__ out)
{
    __shared__ float ts[K2_ROWS][RNK];                 // t, plain f32

    const int tid = threadIdx.x;
    const int cb  = blockIdx.x & (K2_CBLK - 1);        // column block (512 cols)
    const long long rowBase = (long long)(blockIdx.x >> 3) * K2_ROWS;
    const int j = cb * 512 + tid * 4;

    // load t (4 splits), combine: 256 f2-units = 32 rows x 8, 2 per thread
    #pragma unroll
    for (int m = 0; m < 2; m++) {
        const int u = tid + m * K2_THREADS;
        const int row = u >> 3, q = u & 7;
        const float* tp = &g_t[(rowBase + row) * (KSPLIT * RNK) + 2 * q];
        float2 s0 = *reinterpret_cast<const float2*>(tp);
        float2 s1 = *reinterpret_cast<const float2*>(tp + RNK);
        float2 s2 = *reinterpret_cast<const float2*>(tp + 2 * RNK);
        float2 s3 = *reinterpret_cast<const float2*>(tp + 3 * RNK);
        ts[row][2 * q]     = (s0.x + s1.x) + (s2.x + s3.x);
        ts[row][2 * q + 1] = (s0.y + s1.y) + (s2.y + s3.y);
    }

    // B_T for this thread's 4 columns: 8 rank-pairs each, contiguous 64 B/col
    ulonglong2 Bt[4][4];
    #pragma unroll
    for (int c = 0; c < 4; c++) {
        const ulonglong2* bp =
            reinterpret_cast<const ulonglong2*>(g_Bt + (long long)(j + c) * RNK);
        Bt[c][0] = bp[0]; Bt[c][1] = bp[1]; Bt[c][2] = bp[2]; Bt[c][3] = bp[3];
    }

    __syncthreads();

    #pragma unroll 2
    for (int row = 0; row < K2_ROWS; row++) {
        // t rank-pairs, native packed from smem: 4 broadcast LDS.128
        const ulonglong2* tr = reinterpret_cast<const ulonglong2*>(ts[row]);
        ulonglong2 q0 = tr[0], q1 = tr[1], q2 = tr[2], q3 = tr[3];

        float4 o;
        #pragma unroll
        for (int c = 0; c < 4; c++) {
            unsigned long long a0 = 0ULL, a1 = 0ULL;
            ffma2(a0, q0.x, Bt[c][0].x);
            ffma2(a1, q0.y, Bt[c][0].y);
            ffma2(a0, q1.x, Bt[c][1].x);
            ffma2(a1, q1.y, Bt[c][1].y);
            ffma2(a0, q2.x, Bt[c][2].x);
            ffma2(a1, q2.y, Bt[c][2].y);
            ffma2(a0, q3.x, Bt[c][3].x);
            ffma2(a1, q3.y, Bt[c][3].y);
            unsigned long long s = add2(a0, a1);
            float lo, hi; unpk2(lo, hi, s);
            (&o.x)[c] = lo + hi;
        }
        *reinterpret_cast<float4*>(
            out + (rowBase + row) * (long long)DOUT + j) = o;
    }
}

extern "C" void kernel_launch(void* const* d_in, const int* in_sizes, int n_in,
                              void* d_out, int out_size) {
    const float* x = (const float*)d_in[0];   // [4, 2048, 4096]
    const float* A = (const float*)d_in[1];   // [4096, 16]
    const float* B = (const float*)d_in[2];   // [16, 4096]
    float* out = (float*)d_out;               // [4, 2048, 4096]

    lora_k0<<<256, 256>>>(A, B);
    lora_k1<<<K1_GRID, K1_THREADS>>>(x);
    lora_k2<<<K2_GRID, K2_THREADS>>>(out);
}

// round 13
// speedup vs baseline: 1.1078x; 1.1078x over previous
#include <cuda_runtime.h>

#define DIN     4096
#define DOUT    4096
#define RNK     16
#define NROWS   8192            // 4*2048

// ---------------- K1 geometry ----------------
#define K1_THREADS 128
#define K1_RPW     8            // rows per warp
#define K1_ROWS    32           // rows per block (4 warps x 8)
#define KSPLIT     4
#define KQ         (DIN / KSPLIT)        // 1024
#define K1_KT      64                    // k per pipeline tile
#define K1_NST     3
#define K1_TILES   (KQ / K1_KT)          // 16
#define ATP        68                    // A_T row pitch in floats (== 4 mod 32)
#define XS_F       (K1_ROWS * K1_KT)     // 2048 floats x-stage
#define AS_F       (RNK * ATP)           // 1088 floats A_T-stage
#define STG_F      (XS_F + AS_F)         // 3136 floats
#define K1_GRID    (NROWS / K1_ROWS * KSPLIT)   // 1024

// ---------------- K2 geometry ----------------
#define K2_THREADS 128
#define K2_ROWS    32
#define K2_CBLK    8                     // column blocks of 512
#define K2_GRID    ((NROWS / K2_ROWS) * K2_CBLK)   // 2048

// scratch: t partials only
__device__ float g_t[NROWS * KSPLIT * RNK];   // 2 MB

__device__ __forceinline__ unsigned long long pk2(float v) {
    unsigned long long r;
    asm("mov.b64 %0, {%1, %1};" : "=l"(r) : "f"(v));
    return r;
}
__device__ __forceinline__ void ffma2(unsigned long long &acc,
                                      unsigned long long a, unsigned long long b) {
    asm("fma.rn.f32x2 %0, %1, %2, %0;" : "+l"(acc) : "l"(a), "l"(b));
}
__device__ __forceinline__ unsigned long long add2(unsigned long long a,
                                                   unsigned long long b) {
    unsigned long long d;
    asm("add.rn.f32x2 %0, %1, %2;" : "=l"(d) : "l"(a), "l"(b));
    return d;
}
__device__ __forceinline__ void unpk2(float &lo, float &hi, unsigned long long v) {
    asm("mov.b64 {%0, %1}, %2;" : "=f"(lo), "=f"(hi) : "l"(v));
}
__device__ __forceinline__ unsigned su32(const void* p) {
    unsigned a;
    asm("{ .reg .u64 t; cvta.to.shared.u64 t, %1; cvt.u32.u64 %0, t; }"
        : "=r"(a) : "l"(p));
    return a;
}
__device__ __forceinline__ void cpa16(unsigned d, const void* s) {
    asm volatile("cp.async.cg.shared.global [%0], [%1], 16;" :: "r"(d), "l"(s));
}
__device__ __forceinline__ void cpa4(unsigned d, const void* s) {
    asm volatile("cp.async.ca.shared.global [%0], [%1], 4;" :: "r"(d), "l"(s));
}

// ============ K1: t_partial = x @ A  (k-paired f32x2, inline A^T) ============
__global__ void __launch_bounds__(K1_THREADS, 6)
lora_k1(const float* __restrict__ x, const float* __restrict__ A)
{
    __shared__ float sm[K1_NST * STG_F];     // ~36.8 KB: x + A_T tiles

    const int tid  = threadIdx.x;
    const int lane = tid & 31;
    const int warp = tid >> 5;
    const int g    = lane & 7;               // rank-group: owns ranks g, g+8
    const int ksub = lane >> 3;              // k-quarter within a 16-k batch
    const int rb    = blockIdx.x >> 2;
    const int split = blockIdx.x & 3;
    const int k0    = split * KQ;
    const long long rowBase = (long long)rb * K1_ROWS;
    const int       warpRow0 = warp * K1_RPW;
    const unsigned  smb = su32(sm);

    // cp.async tile: x [32 rows x 64 k] (16B) + A^T via 4B transpose granules
    auto issue = [&](int tile, int stg) {
        const unsigned xs = smb + (unsigned)(stg * STG_F) * 4u;
        const unsigned as = xs + XS_F * 4u;
        const long long gk = k0 + tile * K1_KT;
        // x: 512 granules (32 rows x 16), 4 per thread
        #pragma unroll
        for (int m = 0; m < 4; m++) {
            int q   = tid + m * K1_THREADS;
            int row = q >> 4, c = q & 15;
            cpa16(xs + (unsigned)(row * K1_KT + c * 4) * 4u,
                  x + (rowBase + row) * DIN + gk + c * 4);
        }
        // A tile transpose: A[k][r] -> As[r][k]. Granule q = k*16+r is a
        // LINEAR gmem index (A row-major [k][16]) => coalesced 4B loads.
        const float* Ag = A + gk * RNK;
        #pragma unroll
        for (int m = 0; m < 8; m++) {
            int q = tid + m * K1_THREADS;            // 0..1023
            int k = q >> 4, r = q & 15;
            cpa4(as + (unsigned)(r * ATP + k) * 4u, Ag + q);
        }
    };

    issue(0, 0); asm volatile("cp.async.commit_group;");
    issue(1, 1); asm volatile("cp.async.commit_group;");

    // acc[row][h]: f32x2 partial (pair over k) for rank g (h=0) / g+8 (h=1)
    unsigned long long acc[K1_RPW][2];
    #pragma unroll
    for (int r = 0; r < K1_RPW; r++) { acc[r][0] = 0ULL; acc[r][1] = 0ULL; }

    #pragma unroll 1
    for (int t = 0; t < K1_TILES; t++) {
        asm volatile("cp.async.wait_group %0;" :: "n"(1));
        __syncthreads();
        // refill stage (t+2)%3 == (t-1)%3 — consumed before the barrier above
        if (t + 2 < K1_TILES) issue(t + 2, (t + 2) % K1_NST);
        asm volatile("cp.async.commit_group;");

        const float* xs = sm + (t % K1_NST) * STG_F;
        const float* ap = xs + XS_F + g * ATP;          // rank g row of A_T
        const float* xp = xs + warpRow0 * K1_KT + 4 * ksub;

        #pragma unroll
        for (int b = 0; b < K1_KT / 16; b++) {          // 4 batches of 16 k
            const int kb = b * 16 + 4 * ksub;           // lane's 4 k
            ulonglong2 aA = *reinterpret_cast<const ulonglong2*>(ap + kb);
            ulonglong2 aB = *reinterpret_cast<const ulonglong2*>(ap + 8 * ATP + kb);

            #pragma unroll
            for (int r = 0; r < K1_RPW; r++) {
                // x float4 = 2 native packed k-pairs — no MOV needed
                ulonglong2 xv = *reinterpret_cast<const ulonglong2*>(
                                    xp + r * K1_KT + b * 16);
                ffma2(acc[r][0], xv.x, aA.x);
                ffma2(acc[r][0], xv.y, aA.y);
                ffma2(acc[r][1], xv.x, aB.x);
                ffma2(acc[r][1], xv.y, aB.y);
            }
        }
    }

    // reduce across the 4 ksub groups (lane stride 8), then horizontal lo+hi
    #pragma unroll
    for (int r = 0; r < K1_RPW; r++) {
        #pragma unroll
        for (int h = 0; h < 2; h++) {
            acc[r][h] = add2(acc[r][h], __shfl_xor_sync(0xffffffffu, acc[r][h], 8));
            acc[r][h] = add2(acc[r][h], __shfl_xor_sync(0xffffffffu, acc[r][h], 16));
        }
    }
    if (ksub == 0) {                                   // lanes 0..7 (= g)
        #pragma unroll
        for (int r = 0; r < K1_RPW; r++) {
            long long row = rowBase + warpRow0 + r;
            float lo, hi, t0, t1;
            unpk2(lo, hi, acc[r][0]); t0 = lo + hi;
            unpk2(lo, hi, acc[r][1]); t1 = lo + hi;
            float* dst = &g_t[row * (KSPLIT * RNK) + split * RNK];
            dst[g]     = t0;
            dst[g + 8] = t1;
        }
    }
}

// ========= K2: out = (sum_s t_s) @ B  (R11 version, known-good) =========
__global__ void __launch_bounds__(K2_THREADS, 5)
lora_k2(const float* __restrict__ B, float* __restrict__ out)
{
    __shared__ float ts[K2_ROWS][RNK];                 // t, plain f32

    const int tid = threadIdx.x;
    const int cb  = blockIdx.x & (K2_CBLK - 1);        // column block (512 cols)
    const long long rowBase = (long long)(blockIdx.x >> 3) * K2_ROWS;
    const int j = cb * 512 + tid * 4;

    // load t (4 splits), combine: 256 f2-units = 32 rows x 8, 2 per thread
    #pragma unroll
    for (int m = 0; m < 2; m++) {
        const int u = tid + m * K2_THREADS;
        const int row = u >> 3, q = u & 7;
        const float* tp = &g_t[(rowBase + row) * (KSPLIT * RNK) + 2 * q];
        float2 s0 = *reinterpret_cast<const float2*>(tp);
        float2 s1 = *reinterpret_cast<const float2*>(tp + RNK);
        float2 s2 = *reinterpret_cast<const float2*>(tp + 2 * RNK);
        float2 s3 = *reinterpret_cast<const float2*>(tp + 3 * RNK);
        ts[row][2 * q]     = (s0.x + s1.x) + (s2.x + s3.x);
        ts[row][2 * q + 1] = (s0.y + s1.y) + (s2.y + s3.y);
    }

    // B columns for this thread: 16 ranks x 4 cols, cached in registers
    ulonglong2 Breg[RNK];
    #pragma unroll
    for (int r = 0; r < RNK; r++)
        Breg[r] = *reinterpret_cast<const ulonglong2*>(B + (long long)r * DOUT + j);

    __syncthreads();

    #pragma unroll 2
    for (int row = 0; row < K2_ROWS; row++) {
        const float4* tr = reinterpret_cast<const float4*>(ts[row]);
        float4 t0 = tr[0], t1 = tr[1], t2 = tr[2], t3 = tr[3];

        unsigned long long aL0 = 0ULL, aH0 = 0ULL, aL1 = 0ULL, aH1 = 0ULL;
        {
            ffma2(aL0, pk2(t0.x), Breg[0].x);  ffma2(aH0, pk2(t0.x), Breg[0].y);
            ffma2(aL0, pk2(t0.y), Breg[1].x);  ffma2(aH0, pk2(t0.y), Breg[1].y);
            ffma2(aL1, pk2(t0.z), Breg[2].x);  ffma2(aH1, pk2(t0.z), Breg[2].y);
            ffma2(aL1, pk2(t0.w), Breg[3].x);  ffma2(aH1, pk2(t0.w), Breg[3].y);
            ffma2(aL0, pk2(t1.x), Breg[4].x);  ffma2(aH0, pk2(t1.x), Breg[4].y);
            ffma2(aL0, pk2(t1.y), Breg[5].x);  ffma2(aH0, pk2(t1.y), Breg[5].y);
            ffma2(aL1, pk2(t1.z), Breg[6].x);  ffma2(aH1, pk2(t1.z), Breg[6].y);
            ffma2(aL1, pk2(t1.w), Breg[7].x);  ffma2(aH1, pk2(t1.w), Breg[7].y);
            ffma2(aL0, pk2(t2.x), Breg[8].x);  ffma2(aH0, pk2(t2.x), Breg[8].y);
            ffma2(aL0, pk2(t2.y), Breg[9].x);  ffma2(aH0, pk2(t2.y), Breg[9].y);
            ffma2(aL1, pk2(t2.z), Breg[10].x); ffma2(aH1, pk2(t2.z), Breg[10].y);
            ffma2(aL1, pk2(t2.w), Breg[11].x); ffma2(aH1, pk2(t2.w), Breg[11].y);
            ffma2(aL0, pk2(t3.x), Breg[12].x); ffma2(aH0, pk2(t3.x), Breg[12].y);
            ffma2(aL0, pk2(t3.y), Breg[13].x); ffma2(aH0, pk2(t3.y), Breg[13].y);
            ffma2(aL1, pk2(t3.z), Breg[14].x); ffma2(aH1, pk2(t3.z), Breg[14].y);
            ffma2(aL1, pk2(t3.w), Breg[15].x); ffma2(aH1, pk2(t3.w), Breg[15].y);
        }
        ulonglong2 o;
        o.x = add2(aL0, aL1);
        o.y = add2(aH0, aH1);
        *reinterpret_cast<ulonglong2*>(
            out + (rowBase + row) * (long long)DOUT + j) = o;
    }
}

extern "C" void kernel_launch(void* const* d_in, const int* in_sizes, int n_in,
                              void* d_out, int out_size) {
    const float* x = (const float*)d_in[0];   // [4, 2048, 4096]
    const float* A = (const float*)d_in[1];   // [4096, 16]
    const float* B = (const float*)d_in[2];   // [16, 4096]
    float* out = (float*)d_out;               // [4, 2048, 4096]

    lora_k1<<<K1_GRID, K1_THREADS>>>(x, A);
    lora_k2<<<K2_GRID, K2_THREADS>>>(B, out);
}

// round 14
// speedup vs baseline: 1.1859x; 1.0705x over previous
#include <cuda_runtime.h>

#define DIN     4096
#define DOUT    4096
#define RNK     16
#define NROWS   8192            // 4*2048

// ---------------- K1 geometry ----------------
#define K1_THREADS 128
#define K1_RPW     16           // rows per warp
#define K1_ROWS    64           // rows per block (4 warps x 16)
#define KSPLIT     4
#define KQ         (DIN / KSPLIT)        // 1024
#define K1_KT      64                    // k per pipeline tile
#define K1_NST     3
#define K1_TILES   (KQ / K1_KT)          // 16
#define ATP        68                    // A_T row pitch in floats (== 4 mod 32)
#define XS_F       (K1_ROWS * K1_KT)     // 4096 floats x-stage
#define AS_F       (RNK * ATP)           // 1088 floats A_T-stage
#define STG_F      (XS_F + AS_F)         // 5184 floats
#define K1_GRID    (NROWS / K1_ROWS * KSPLIT)   // 512

// ---------------- K2 geometry ----------------
#define K2_THREADS 128
#define K2_ROWS    32
#define K2_CBLK    8                     // column blocks of 512
#define K2_GRID    ((NROWS / K2_ROWS) * K2_CBLK)   // 2048

// scratch: t partials + transposed A
__device__ float g_t[NROWS * KSPLIT * RNK];   // 2 MB
__device__ float g_At[RNK * DIN];             // 256 KB: A_T[r][k]

__device__ __forceinline__ unsigned long long pk2(float v) {
    unsigned long long r;
    asm("mov.b64 %0, {%1, %1};" : "=l"(r) : "f"(v));
    return r;
}
__device__ __forceinline__ void ffma2(unsigned long long &acc,
                                      unsigned long long a, unsigned long long b) {
    asm("fma.rn.f32x2 %0, %1, %2, %0;" : "+l"(acc) : "l"(a), "l"(b));
}
__device__ __forceinline__ unsigned long long add2(unsigned long long a,
                                                   unsigned long long b) {
    unsigned long long d;
    asm("add.rn.f32x2 %0, %1, %2;" : "=l"(d) : "l"(a), "l"(b));
    return d;
}
__device__ __forceinline__ void unpk2(float &lo, float &hi, unsigned long long v) {
    asm("mov.b64 {%0, %1}, %2;" : "=f"(lo), "=f"(hi) : "l"(v));
}
__device__ __forceinline__ unsigned su32(const void* p) {
    unsigned a;
    asm("{ .reg .u64 t; cvta.to.shared.u64 t, %1; cvt.u32.u64 %0, t; }"
        : "=r"(a) : "l"(p));
    return a;
}
__device__ __forceinline__ void cpa16(unsigned d, const void* s) {
    asm volatile("cp.async.cg.shared.global [%0], [%1], 16;" :: "r"(d), "l"(s));
}

// ============ K0: g_At = A^T  (one-time, tiny) ============
__global__ void lora_k0(const float* __restrict__ A) {
    const int r = blockIdx.y;                          // 0..15
    const int k = blockIdx.x * 256 + threadIdx.x;      // 0..4095
    g_At[r * DIN + k] = A[(long long)k * RNK + r];
}

// ===== K1: t_partial = x @ A  (k-paired f32x2, RPW=16) =====
__global__ void __launch_bounds__(K1_THREADS, 3)
lora_k1(const float* __restrict__ x)
{
    __shared__ float sm[K1_NST * STG_F];     // ~62.2 KB: x + A_T tiles

    const int tid  = threadIdx.x;
    const int lane = tid & 31;
    const int warp = tid >> 5;
    const int g    = lane & 7;               // rank-group: owns ranks g, g+8
    const int ksub = lane >> 3;              // k-quarter within a 16-k batch
    const int rb    = blockIdx.x >> 2;
    const int split = blockIdx.x & 3;
    const int k0    = split * KQ;
    const long long rowBase = (long long)rb * K1_ROWS;
    const int       warpRow0 = warp * K1_RPW;
    const unsigned  smb = su32(sm);

    // cp.async tile: x [64 rows x 64 k] + A_T [16 ranks x 64 k], 16B granules
    auto issue = [&](int tile, int stg) {
        const unsigned xs = smb + (unsigned)(stg * STG_F) * 4u;
        const unsigned as = xs + XS_F * 4u;
        const long long gk = k0 + tile * K1_KT;
        // x: 1024 granules (64 rows x 16), 8 per thread
        #pragma unroll
        for (int m = 0; m < 8; m++) {
            int q   = tid + m * K1_THREADS;
            int row = q >> 4, c = q & 15;
            cpa16(xs + (unsigned)(row * K1_KT + c * 4) * 4u,
                  x + (rowBase + row) * DIN + gk + c * 4);
        }
        // A_T: 256 granules (16 ranks x 16), 2 per thread
        #pragma unroll
        for (int m = 0; m < 2; m++) {
            int q = tid + m * K1_THREADS;
            int r = q >> 4, c = q & 15;
            cpa16(as + (unsigned)(r * ATP + c * 4) * 4u,
                  g_At + (long long)r * DIN + gk + c * 4);
        }
    };

    issue(0, 0); asm volatile("cp.async.commit_group;");
    issue(1, 1); asm volatile("cp.async.commit_group;");

    // acc[row][h]: f32x2 partial (pair over k) for rank g (h=0) / g+8 (h=1)
    unsigned long long acc[K1_RPW][2];
    #pragma unroll
    for (int r = 0; r < K1_RPW; r++) { acc[r][0] = 0ULL; acc[r][1] = 0ULL; }

    #pragma unroll 1
    for (int t = 0; t < K1_TILES; t++) {
        asm volatile("cp.async.wait_group %0;" :: "n"(1));
        __syncthreads();
        // refill stage (t+2)%3 == (t-1)%3 — consumed before the barrier above
        if (t + 2 < K1_TILES) issue(t + 2, (t + 2) % K1_NST);
        asm volatile("cp.async.commit_group;");

        const float* xs = sm + (t % K1_NST) * STG_F;
        const float* ap = xs + XS_F + g * ATP;          // rank g row of A_T
        const float* xp = xs + warpRow0 * K1_KT + 4 * ksub;

        #pragma unroll
        for (int b = 0; b < K1_KT / 16; b++) {          // 4 batches of 16 k
            const int kb = b * 16 + 4 * ksub;           // lane's 4 k
            ulonglong2 aA = *reinterpret_cast<const ulonglong2*>(ap + kb);
            ulonglong2 aB = *reinterpret_cast<const ulonglong2*>(ap + 8 * ATP + kb);

            #pragma unroll
            for (int r = 0; r < K1_RPW; r++) {
                // x float4 = 2 native packed k-pairs — no MOV needed
                ulonglong2 xv = *reinterpret_cast<const ulonglong2*>(
                                    xp + r * K1_KT + b * 16);
                ffma2(acc[r][0], xv.x, aA.x);
                ffma2(acc[r][0], xv.y, aA.y);
                ffma2(acc[r][1], xv.x, aB.x);
                ffma2(acc[r][1], xv.y, aB.y);
            }
        }
    }

    // reduce across the 4 ksub groups (lane stride 8), then horizontal lo+hi
    #pragma unroll
    for (int r = 0; r < K1_RPW; r++) {
        #pragma unroll
        for (int h = 0; h < 2; h++) {
            acc[r][h] = add2(acc[r][h], __shfl_xor_sync(0xffffffffu, acc[r][h], 8));
            acc[r][h] = add2(acc[r][h], __shfl_xor_sync(0xffffffffu, acc[r][h], 16));
        }
    }
    if (ksub == 0) {                                   // lanes 0..7 (= g)
        #pragma unroll
        for (int r = 0; r < K1_RPW; r++) {
            long long row = rowBase + warpRow0 + r;
            float lo, hi, t0, t1;
            unpk2(lo, hi, acc[r][0]); t0 = lo + hi;
            unpk2(lo, hi, acc[r][1]); t1 = lo + hi;
            float* dst = &g_t[row * (KSPLIT * RNK) + split * RNK];
            dst[g]     = t0;
            dst[g + 8] = t1;
        }
    }
}

// ========= K2: out = (sum_s t_s) @ B  (R11 version, known-good) =========
__global__ void __launch_bounds__(K2_THREADS, 5)
lora_k2(const float* __restrict__ B, float* __restrict__ out)
{
    __shared__ float ts[K2_ROWS][RNK];                 // t, plain f32

    const int tid = threadIdx.x;
    const int cb  = blockIdx.x & (K2_CBLK - 1);        // column block (512 cols)
    const long long rowBase = (long long)(blockIdx.x >> 3) * K2_ROWS;
    const int j = cb * 512 + tid * 4;

    // load t (4 splits), combine: 256 f2-units = 32 rows x 8, 2 per thread
    #pragma unroll
    for (int m = 0; m < 2; m++) {
        const int u = tid + m * K2_THREADS;
        const int row = u >> 3, q = u & 7;
        const float* tp = &g_t[(rowBase + row) * (KSPLIT * RNK) + 2 * q];
        float2 s0 = *reinterpret_cast<const float2*>(tp);
        float2 s1 = *reinterpret_cast<const float2*>(tp + RNK);
        float2 s2 = *reinterpret_cast<const float2*>(tp + 2 * RNK);
        float2 s3 = *reinterpret_cast<const float2*>(tp + 3 * RNK);
        ts[row][2 * q]     = (s0.x + s1.x) + (s2.x + s3.x);
        ts[row][2 * q + 1] = (s0.y + s1.y) + (s2.y + s3.y);
    }

    // B columns for this thread: 16 ranks x 4 cols, cached in registers
    ulonglong2 Breg[RNK];
    #pragma unroll
    for (int r = 0; r < RNK; r++)
        Breg[r] = *reinterpret_cast<const ulonglong2*>(B + (long long)r * DOUT + j);

    __syncthreads();

    #pragma unroll 2
    for (int row = 0; row < K2_ROWS; row++) {
        const float4* tr = reinterpret_cast<const float4*>(ts[row]);
        float4 t0 = tr[0], t1 = tr[1], t2 = tr[2], t3 = tr[3];

        unsigned long long aL0 = 0ULL, aH0 = 0ULL, aL1 = 0ULL, aH1 = 0ULL;
        {
            ffma2(aL0, pk2(t0.x), Breg[0].x);  ffma2(aH0, pk2(t0.x), Breg[0].y);
            ffma2(aL0, pk2(t0.y), Breg[1].x);  ffma2(aH0, pk2(t0.y), Breg[1].y);
            ffma2(aL1, pk2(t0.z), Breg[2].x);  ffma2(aH1, pk2(t0.z), Breg[2].y);
            ffma2(aL1, pk2(t0.w), Breg[3].x);  ffma2(aH1, pk2(t0.w), Breg[3].y);
            ffma2(aL0, pk2(t1.x), Breg[4].x);  ffma2(aH0, pk2(t1.x), Breg[4].y);
            ffma2(aL0, pk2(t1.y), Breg[5].x);  ffma2(aH0, pk2(t1.y), Breg[5].y);
            ffma2(aL1, pk2(t1.z), Breg[6].x);  ffma2(aH1, pk2(t1.z), Breg[6].y);
            ffma2(aL1, pk2(t1.w), Breg[7].x);  ffma2(aH1, pk2(t1.w), Breg[7].y);
            ffma2(aL0, pk2(t2.x), Breg[8].x);  ffma2(aH0, pk2(t2.x), Breg[8].y);
            ffma2(aL0, pk2(t2.y), Breg[9].x);  ffma2(aH0, pk2(t2.y), Breg[9].y);
            ffma2(aL1, pk2(t2.z), Breg[10].x); ffma2(aH1, pk2(t2.z), Breg[10].y);
            ffma2(aL1, pk2(t2.w), Breg[11].x); ffma2(aH1, pk2(t2.w), Breg[11].y);
            ffma2(aL0, pk2(t3.x), Breg[12].x); ffma2(aH0, pk2(t3.x), Breg[12].y);
            ffma2(aL0, pk2(t3.y), Breg[13].x); ffma2(aH0, pk2(t3.y), Breg[13].y);
            ffma2(aL1, pk2(t3.z), Breg[14].x); ffma2(aH1, pk2(t3.z), Breg[14].y);
            ffma2(aL1, pk2(t3.w), Breg[15].x); ffma2(aH1, pk2(t3.w), Breg[15].y);
        }
        ulonglong2 o;
        o.x = add2(aL0, aL1);
        o.y = add2(aH0, aH1);
        *reinterpret_cast<ulonglong2*>(
            out + (rowBase + row) * (long long)DOUT + j) = o;
    }
}

extern "C" void kernel_launch(void* const* d_in, const int* in_sizes, int n_in,
                              void* d_out, int out_size) {
    const float* x = (const float*)d_in[0];   // [4, 2048, 4096]
    const float* A = (const float*)d_in[1];   // [4096, 16]
    const float* B = (const float*)d_in[2];   // [16, 4096]
    float* out = (float*)d_out;               // [4, 2048, 4096]

    lora_k0<<<dim3(16, 16), 256>>>(A);
    lora_k1<<<K1_GRID, K1_THREADS>>>(x);
    lora_k2<<<K2_GRID, K2_THREADS>>>(B, out);
}